// round 8
// baseline (speedup 1.0000x reference)
#include <cuda_runtime.h>

#define NAG    12
#define NENV   4096
#define NNODE  (NENV*NAG)
#define TPB    192

// shared float offsets
#define OFF_WA   0        // 4096 (64x64 half of We1/Wh1)
#define OFF_WB   4096     // 4096 (Wemb / We2 / Wh2)
#define OFF_H    8192     // 12x64
#define OFF_P2   8960     // P2 float2[12][32]
#define OFF_AGG  9728     // 12x64
#define OFF_XS0  10496    // 144
#define OFF_XS1  10640    // 144
#define OFF_RAD  10784    // 132x4
#define OFF_MS   11312    // 6 warps x 384 = 2304 ; h0s + t1s alias (phase-disjoint)
#define OFF_H0S  OFF_MS
#define OFF_T1S  OFF_MS
#define SMEM_FLOATS 13616
#define SMEM_BYTES  (SMEM_FLOATS*4)

#define COMP(v,q) ((q)==0?(v).x:(q)==1?(v).y:(q)==2?(v).z:(v).w)

__device__ __forceinline__ float siluf(float v) { return v / (1.0f + __expf(-v)); }

__device__ __forceinline__ void stage64(float* dst, const float* src, int tid) {
    float4* q = (float4*)dst;
    const float4* g = (const float4*)src;
    for (int i = tid; i < 1024; i += TPB) q[i] = __ldg(&g[i]);
}

extern "C" __global__ void __launch_bounds__(TPB, 4)
egnn_kernel(const float* __restrict__ h0,   const float* __restrict__ x0,
            const float* __restrict__ Wemb, const float* __restrict__ bemb,
            const float* __restrict__ We1,  const float* __restrict__ be1,
            const float* __restrict__ We2,  const float* __restrict__ be2,
            const float* __restrict__ Wx,   const float* __restrict__ bx,
            const float* __restrict__ Wh1,  const float* __restrict__ bh1,
            const float* __restrict__ Wh2,  const float* __restrict__ bh2,
            const float* __restrict__ w_act,const float* __restrict__ log_std,
            float* __restrict__ out)
{
    extern __shared__ float sm[];
    float* WA  = sm + OFF_WA;
    float* WB  = sm + OFF_WB;
    float* hs  = sm + OFF_H;
    float* P2p = sm + OFF_P2;
    float* agg = sm + OFF_AGG;
    float* xs0 = sm + OFF_XS0;
    float* xs1 = sm + OFF_XS1;
    float* rad = sm + OFF_RAD;
    float* h0s = sm + OFF_H0S;
    float* t1s = sm + OFF_T1S;
    float* ms  = sm + OFF_MS;

    const int tid  = threadIdx.x;
    const int w    = tid >> 5;
    const int lane = tid & 31;
    const int env  = blockIdx.x;
    const int base = env * NAG;
    const int iA = 2 * w, iB = 2 * w + 1;

    // ---------- phase 0: stage x, h0, W_embed ; embed ----------
    if (tid < NAG * NAG) xs0[tid] = __ldg(&x0[base * 12 + tid]);
    for (int t = tid; t < NAG * 32; t += TPB) h0s[t] = __ldg(&h0[base * 32 + t]);
    {
        float4* q = (float4*)WB;
        const float4* g = (const float4*)Wemb;
        for (int i = tid; i < 512; i += TPB) q[i] = __ldg(&g[i]);
    }
    __syncthreads();
    {   // h = h0 @ Wemb + bemb (2 nodes per warp)
        float a0A = __ldg(&bemb[lane]),      a1A = __ldg(&bemb[lane + 32]);
        float a0B = a0A, a1B = a1A;
        #pragma unroll
        for (int k4 = 0; k4 < 8; k4++) {
            float4 hA4 = *(const float4*)&h0s[iA*32 + k4*4];
            float4 hB4 = *(const float4*)&h0s[iB*32 + k4*4];
            #pragma unroll
            for (int q = 0; q < 4; q++) {
                int k = k4*4 + q;
                float w0 = WB[k*64 + lane], w1 = WB[k*64 + lane + 32];
                float hA = COMP(hA4,q), hB = COMP(hB4,q);
                a0A += hA*w0; a1A += hA*w1;
                a0B += hB*w0; a1B += hB*w1;
            }
        }
        hs[iA*64 + lane] = a0A; hs[iA*64 + lane + 32] = a1A;
        hs[iB*64 + lane] = a0B; hs[iB*64 + lane + 32] = a1B;
    }

    // ---------- layers ----------
    for (int l = 0; l < 2; l++) {
        __syncthreads();
        float* xsr = (l == 0) ? xs0 : xs1;
        float* xsw = (l == 0) ? xs1 : xs0;
        stage64(WA, We1 + l * 8448, tid);       // We1 rows 0..63
        stage64(WB, We2 + l * 4096, tid);
        if (tid < 132) {   // radial per edge
            int e = tid, i = e / 11, tt = e - 11 * i, j = tt + (tt >= i);
            float s0 = 0.f, s1 = 0.f, s2 = 0.f, s3 = 0.f;
            #pragma unroll
            for (int d = 0; d < 3; d++) {
                float d0 = xsr[i*12 + d*4 + 0] - xsr[j*12 + d*4 + 0]; s0 += d0*d0;
                float d1 = xsr[i*12 + d*4 + 1] - xsr[j*12 + d*4 + 1]; s1 += d1*d1;
                float d2 = xsr[i*12 + d*4 + 2] - xsr[j*12 + d*4 + 2]; s2 += d2*d2;
                float d3 = xsr[i*12 + d*4 + 3] - xsr[j*12 + d*4 + 3]; s3 += d3*d3;
            }
            ((float4*)rad)[e] = make_float4(s0, s1, s2, s3);
        }
        __syncthreads();

        // ---- P1 pass: hi @ We1[0:64] + be1 (kept in regs) ----
        float PiA0, PiA1, PiB0, PiB1;
        {
            float b0 = __ldg(&be1[l*64 + lane]), b1 = __ldg(&be1[l*64 + lane + 32]);
            float a0A = b0, a1A = b1, a0B = b0, a1B = b1;
            #pragma unroll
            for (int k4 = 0; k4 < 16; k4++) {
                float4 hA4 = *(const float4*)&hs[iA*64 + k4*4];
                float4 hB4 = *(const float4*)&hs[iB*64 + k4*4];
                #pragma unroll
                for (int q = 0; q < 4; q++) {
                    int k = k4*4 + q;
                    float w0 = WA[k*64 + lane], w1 = WA[k*64 + lane + 32];
                    float hA = COMP(hA4,q), hB = COMP(hB4,q);
                    a0A += hA*w0; a1A += hA*w1;
                    a0B += hB*w0; a1B += hB*w1;
                }
            }
            PiA0 = a0A; PiA1 = a1A; PiB0 = a0B; PiB1 = a1B;
        }
        __syncthreads();
        stage64(WA, We1 + l * 8448 + 4096, tid);   // We1 rows 64..127
        __syncthreads();
        // ---- P2 pass: hj @ We1[64:128] -> smem ----
        {
            float a2A = 0.f, a3A = 0.f, a2B = 0.f, a3B = 0.f;
            #pragma unroll
            for (int k4 = 0; k4 < 16; k4++) {
                float4 hA4 = *(const float4*)&hs[iA*64 + k4*4];
                float4 hB4 = *(const float4*)&hs[iB*64 + k4*4];
                #pragma unroll
                for (int q = 0; q < 4; q++) {
                    int k = k4*4 + q;
                    float w2 = WA[k*64 + lane], w3 = WA[k*64 + lane + 32];
                    float hA = COMP(hA4,q), hB = COMP(hB4,q);
                    a2A += hA*w2; a3A += hA*w3;
                    a2B += hB*w2; a3B += hB*w3;
                }
            }
            ((float2*)P2p)[iA*32 + lane] = make_float2(a2A, a3A);
            ((float2*)P2p)[iB*32 + lane] = make_float2(a2B, a3B);
        }
        __syncthreads();

        // ---- edge phase: warp owns nodes iA, iB (22 edges, batch 6) ----
        {
            const float4 wxA = __ldg((const float4*)&Wx[l*256 + lane*4]);
            const float4 wxB = __ldg((const float4*)&Wx[l*256 + (lane+32)*4]);
            const float4 bxv = __ldg((const float4*)&bx[l*4]);
            const float be2a = __ldg(&be2[l*64 + lane]);
            const float be2b = __ldg(&be2[l*64 + lane + 32]);
            const float xiA = (lane < 12) ? xsr[iA*12 + lane] : 0.f;
            const float xiB = (lane < 12) ? xsr[iB*12 + lane] : 0.f;
            float agA0 = 0.f, agB0 = 0.f, agA1 = 0.f, agB1 = 0.f;
            float dx0 = 0.f, dx1 = 0.f;
            float* msw = ms + w * 384;
            const bool lb0 = lane & 1, lb1 = lane & 2;

            #pragma unroll
            for (int g0 = 0; g0 < 22; g0 += 6) {
                const int cnt = (22 - g0 < 6) ? (22 - g0) : 6;
                // MLP1 (radial-row weights loaded per pass; scoped regs)
                {
                    float wrA[4], wrB[4];
                    #pragma unroll
                    for (int v = 0; v < 4; v++) {
                        wrA[v] = __ldg(&We1[l*8448 + (128+v)*64 + lane]);
                        wrB[v] = __ldg(&We1[l*8448 + (128+v)*64 + lane + 32]);
                    }
                    #pragma unroll
                    for (int gg = 0; gg < 6; gg++) if (gg < cnt) {
                        const int t = g0 + gg;
                        const int i  = (t < 11) ? iA : iB;
                        const int tt = (t < 11) ? t : (t - 11);
                        const int j  = tt + (tt >= i);
                        float2 pj = ((const float2*)P2p)[j*32 + lane];
                        float4 rv = ((const float4*)rad)[i*11 + tt];
                        float P1a = (t < 11) ? PiA0 : PiB0;
                        float P1b = (t < 11) ? PiA1 : PiB1;
                        float aA = P1a + pj.x
                                 + rv.x*wrA[0] + rv.y*wrA[1] + rv.z*wrA[2] + rv.w*wrA[3];
                        float aB = P1b + pj.y
                                 + rv.x*wrB[0] + rv.y*wrB[1] + rv.z*wrB[2] + rv.w*wrB[3];
                        msw[gg*64 + lane]      = siluf(aA);
                        msw[gg*64 + lane + 32] = siluf(aB);
                    }
                }
                __syncwarp();
                // MLP2: weights read once per k4 for up to 6 edges
                float acc0[6], acc1[6];
                #pragma unroll
                for (int gg = 0; gg < 6; gg++) { acc0[gg] = be2a; acc1[gg] = be2b; }
                #pragma unroll
                for (int k4 = 0; k4 < 16; k4++) {
                    float w00 = WB[(4*k4+0)*64 + lane];
                    float w01 = WB[(4*k4+1)*64 + lane];
                    float w02 = WB[(4*k4+2)*64 + lane];
                    float w03 = WB[(4*k4+3)*64 + lane];
                    float w10 = WB[(4*k4+0)*64 + lane + 32];
                    float w11 = WB[(4*k4+1)*64 + lane + 32];
                    float w12 = WB[(4*k4+2)*64 + lane + 32];
                    float w13 = WB[(4*k4+3)*64 + lane + 32];
                    #pragma unroll
                    for (int gg = 0; gg < 6; gg++) if (gg < cnt) {
                        float4 aq = *(const float4*)&msw[gg*64 + k4*4];
                        acc0[gg] += aq.x*w00 + aq.y*w01 + aq.z*w02 + aq.w*w03;
                        acc1[gg] += aq.x*w10 + aq.y*w11 + aq.z*w12 + aq.w*w13;
                    }
                }
                // epilogue: 6-shuffle multi-value reduce
                #pragma unroll
                for (int gg = 0; gg < 6; gg++) if (gg < cnt) {
                    const int t = g0 + gg;
                    const int tt = (t < 11) ? t : (t - 11);
                    const int i  = (t < 11) ? iA : iB;
                    const int j  = tt + (tt >= i);
                    float m0  = siluf(acc0[gg]);
                    float m1v = siluf(acc1[gg]);
                    if (t < 11) { agA0 += m0; agB0 += m1v; }
                    else        { agA1 += m0; agB1 += m1v; }
                    float p0 = m0*wxA.x + m1v*wxB.x;
                    float p1 = m0*wxA.y + m1v*wxB.y;
                    float p2 = m0*wxA.z + m1v*wxB.z;
                    float p3 = m0*wxA.w + m1v*wxB.w;
                    float sA = __shfl_xor_sync(0xffffffffu, lb0 ? p0 : p1, 1);
                    float A  = (lb0 ? p1 : p0) + sA;
                    float sC = __shfl_xor_sync(0xffffffffu, lb0 ? p2 : p3, 1);
                    float C  = (lb0 ? p3 : p2) + sC;
                    float sR = __shfl_xor_sync(0xffffffffu, lb1 ? A : C, 2);
                    float R  = (lb1 ? C : A) + sR;
                    R += __shfl_xor_sync(0xffffffffu, R, 4);
                    R += __shfl_xor_sync(0xffffffffu, R, 8);
                    R += __shfl_xor_sync(0xffffffffu, R, 16);
                    if (lane < 12) {
                        int v = lane & 3;
                        float wc = R + ((v == 0) ? bxv.x : (v == 1) ? bxv.y :
                                        (v == 2) ? bxv.z : bxv.w);
                        float xi = (t < 11) ? xiA : xiB;
                        float d  = (xi - xsr[j*12 + lane]) * wc;
                        if (t < 11) dx0 += d; else dx1 += d;
                    }
                }
                __syncwarp();
            }
            agg[iA*64 + lane]      = agA0;
            agg[iA*64 + lane + 32] = agB0;
            agg[iB*64 + lane]      = agA1;
            agg[iB*64 + lane + 32] = agB1;
            if (lane < 12) {
                xsw[iA*12 + lane] = xiA + dx0 * (1.0f / 11.0f);
                xsw[iB*12 + lane] = xiB + dx1 * (1.0f / 11.0f);
            }
        }
        __syncthreads();
        stage64(WA, Wh1 + l * 8192, tid);       // Wh1 rows 0..63
        stage64(WB, Wh2 + l * 4096, tid);
        __syncthreads();

        // t1 pass1: h @ Wh1[0:64] (accumulators persist across restage)
        float a0A, a1A, a0B, a1B;
        {
            float b0 = __ldg(&bh1[l*64 + lane]), b1 = __ldg(&bh1[l*64 + lane + 32]);
            a0A = b0; a1A = b1; a0B = b0; a1B = b1;
            #pragma unroll
            for (int k4 = 0; k4 < 16; k4++) {
                float4 hA4 = *(const float4*)&hs[iA*64 + k4*4];
                float4 hB4 = *(const float4*)&hs[iB*64 + k4*4];
                #pragma unroll
                for (int q = 0; q < 4; q++) {
                    int k = k4*4 + q;
                    float w0 = WA[k*64 + lane], w1 = WA[k*64 + lane + 32];
                    float hA = COMP(hA4,q), hB = COMP(hB4,q);
                    a0A += hA*w0; a1A += hA*w1;
                    a0B += hB*w0; a1B += hB*w1;
                }
            }
        }
        __syncthreads();
        stage64(WA, Wh1 + l * 8192 + 4096, tid);   // Wh1 rows 64..127
        __syncthreads();
        // t1 pass2: agg @ Wh1[64:128], silu -> t1s (= ms scratch, free now)
        {
            #pragma unroll
            for (int k4 = 0; k4 < 16; k4++) {
                float4 gA4 = *(const float4*)&agg[iA*64 + k4*4];
                float4 gB4 = *(const float4*)&agg[iB*64 + k4*4];
                #pragma unroll
                for (int q = 0; q < 4; q++) {
                    int k = k4*4 + q;
                    float w0 = WA[k*64 + lane], w1 = WA[k*64 + lane + 32];
                    float gA = COMP(gA4,q), gB = COMP(gB4,q);
                    a0A += gA*w0; a1A += gA*w1;
                    a0B += gB*w0; a1B += gB*w1;
                }
            }
            t1s[iA*64 + lane]      = siluf(a0A);
            t1s[iA*64 + lane + 32] = siluf(a1A);
            t1s[iB*64 + lane]      = siluf(a0B);
            t1s[iB*64 + lane + 32] = siluf(a1B);
        }
        __syncthreads();
        // h += t1 @ Wh2 + bh2
        {
            float b0 = __ldg(&bh2[l*64 + lane]), b1 = __ldg(&bh2[l*64 + lane + 32]);
            float c0A = b0, c1A = b1, c0B = b0, c1B = b1;
            #pragma unroll
            for (int k4 = 0; k4 < 16; k4++) {
                float4 tA4 = *(const float4*)&t1s[iA*64 + k4*4];
                float4 tB4 = *(const float4*)&t1s[iB*64 + k4*4];
                #pragma unroll
                for (int q = 0; q < 4; q++) {
                    int k = k4*4 + q;
                    float w0 = WB[k*64 + lane], w1 = WB[k*64 + lane + 32];
                    float tA = COMP(tA4,q), tB = COMP(tB4,q);
                    c0A += tA*w0; c1A += tA*w1;
                    c0B += tB*w0; c1B += tB*w1;
                }
            }
            hs[iA*64 + lane]      += c0A;
            hs[iA*64 + lane + 32] += c1A;
            hs[iB*64 + lane]      += c0B;
            hs[iB*64 + lane + 32] += c1B;
        }
    }
    __syncthreads();
    // ---------- output: mu = x . w_act (final x in xs0) ----------
    if (tid < NAG * 3) {
        int a = tid / 3, d = tid - 3 * a;
        float mu = 0.f;
        #pragma unroll
        for (int v = 0; v < 4; v++) mu += xs0[a*12 + d*4 + v] * __ldg(&w_act[v]);
        out[(base + a) * 3 + d] = mu;
        out[NNODE * 3 + (base + a) * 3 + d] =
            -__ldg(&log_std[d]) - 0.91893853320467274178f;
    }
}

extern "C" void kernel_launch(void* const* d_in, const int* in_sizes, int n_in,
                              void* d_out, int out_size)
{
    (void)in_sizes; (void)n_in; (void)out_size;
    cudaFuncSetAttribute(egnn_kernel,
                         cudaFuncAttributeMaxDynamicSharedMemorySize, SMEM_BYTES);
    egnn_kernel<<<NENV, TPB, SMEM_BYTES>>>(
        (const float*)d_in[0],  (const float*)d_in[1],
        (const float*)d_in[2],  (const float*)d_in[3],
        (const float*)d_in[4],  (const float*)d_in[5],
        (const float*)d_in[6],  (const float*)d_in[7],
        (const float*)d_in[8],  (const float*)d_in[9],
        (const float*)d_in[10], (const float*)d_in[11],
        (const float*)d_in[12], (const float*)d_in[13],
        (const float*)d_in[14], (const float*)d_in[15],
        (float*)d_out);
}

// round 9
// speedup vs baseline: 1.1160x; 1.1160x over previous
#include <cuda_runtime.h>

#define NAG    12
#define NENV   4096
#define NNODE  (NENV*NAG)
#define TPB    192

// shared float offsets
#define OFF_WA   0        // 8192 paired-k (We1[0:128] / Wh1)
#define OFF_WB   8192     // 4096 paired-k (Wemb / We2 / Wh2)
#define OFF_H    12288    // 12x64
#define OFF_P2   13056    // P2 float2[12][32] ; reused as t1 [12][64]
#define OFF_AGG  13824    // 12x64
#define OFF_XS0  14592    // 144
#define OFF_XS1  14736    // 144
#define OFF_RAD  14880    // 132x4
#define OFF_H0S  15408    // 12x32
#define OFF_MS   15792    // 6 warps x 384
#define SMEM_FLOATS 18096
#define SMEM_BYTES  (SMEM_FLOATS*4)

typedef unsigned long long u64;

__device__ __forceinline__ float siluf(float v) { return v / (1.0f + __expf(-v)); }
__device__ __forceinline__ u64 ld64s(const float* p) { return *(const u64*)p; }
__device__ __forceinline__ void fma2(u64& d, u64 a, u64 b) {
    asm("fma.rn.f32x2 %0, %1, %2, %0;" : "+l"(d) : "l"(a), "l"(b));
}
__device__ __forceinline__ u64 pk(float lo, float hi) {
    u64 r; asm("mov.b64 %0, {%1, %2};" : "=l"(r) : "f"(lo), "f"(hi)); return r;
}
__device__ __forceinline__ float hsum(u64 v) {
    float lo, hi; asm("mov.b64 {%0, %1}, %2;" : "=f"(lo), "=f"(hi) : "l"(v));
    return lo + hi;
}

// stage K2 k-pairs of a [2*K2 x 64] row-major matrix into paired layout:
// dst2[k2*64 + c] = (src[2k2][c], src[2k2+1][c])
template<int K2>
__device__ __forceinline__ void stagePairs(float* dst, const float* src, int tid) {
    const float4* s4 = (const float4*)src;
    float2* d2 = (float2*)dst;
    for (int f = tid; f < K2 * 16; f += TPB) {
        int k2 = f >> 4, c4 = f & 15;
        float4 r0 = __ldg(&s4[(2*k2)*16 + c4]);
        float4 r1 = __ldg(&s4[(2*k2+1)*16 + c4]);
        float2* d = d2 + k2*64 + c4*4;
        d[0] = make_float2(r0.x, r1.x);
        d[1] = make_float2(r0.y, r1.y);
        d[2] = make_float2(r0.z, r1.z);
        d[3] = make_float2(r0.w, r1.w);
    }
}

extern "C" __global__ void __launch_bounds__(TPB, 3)
egnn_kernel(const float* __restrict__ h0,   const float* __restrict__ x0,
            const float* __restrict__ Wemb, const float* __restrict__ bemb,
            const float* __restrict__ We1,  const float* __restrict__ be1,
            const float* __restrict__ We2,  const float* __restrict__ be2,
            const float* __restrict__ Wx,   const float* __restrict__ bx,
            const float* __restrict__ Wh1,  const float* __restrict__ bh1,
            const float* __restrict__ Wh2,  const float* __restrict__ bh2,
            const float* __restrict__ w_act,const float* __restrict__ log_std,
            float* __restrict__ out)
{
    extern __shared__ float sm[];
    float* WA  = sm + OFF_WA;
    float* WB  = sm + OFF_WB;
    const u64* WA2 = (const u64*)WA;   // [k2*64 + c]
    const u64* WB2 = (const u64*)WB;
    float* hs  = sm + OFF_H;
    float* P2p = sm + OFF_P2;
    float* t1s = sm + OFF_P2;          // phase-disjoint reuse
    float* agg = sm + OFF_AGG;
    float* xs0 = sm + OFF_XS0;
    float* xs1 = sm + OFF_XS1;
    float* rad = sm + OFF_RAD;
    float* h0s = sm + OFF_H0S;
    float* ms  = sm + OFF_MS;

    const int tid  = threadIdx.x;
    const int w    = tid >> 5;
    const int lane = tid & 31;
    const int env  = blockIdx.x;
    const int base = env * NAG;
    const int iA = 2 * w, iB = 2 * w + 1;

    // ---------- phase 0: stage x, h0, W_embed(paired) ; embed ----------
    if (tid < NAG * NAG) xs0[tid] = __ldg(&x0[base * 12 + tid]);
    for (int t = tid; t < NAG * 32; t += TPB) h0s[t] = __ldg(&h0[base * 32 + t]);
    stagePairs<16>(WB, Wemb, tid);
    __syncthreads();
    {   // h = h0 @ Wemb + bemb (2 nodes per warp, FFMA2 over k-pairs)
        u64 a0A = 0ull, a1A = 0ull, a0B = 0ull, a1B = 0ull;
        #pragma unroll
        for (int k2 = 0; k2 < 16; k2++) {
            u64 hpA = ld64s(&h0s[iA*32 + 2*k2]);
            u64 hpB = ld64s(&h0s[iB*32 + 2*k2]);
            u64 w0 = WB2[k2*64 + lane], w1 = WB2[k2*64 + lane + 32];
            fma2(a0A, w0, hpA); fma2(a1A, w1, hpA);
            fma2(a0B, w0, hpB); fma2(a1B, w1, hpB);
        }
        float b0 = __ldg(&bemb[lane]), b1 = __ldg(&bemb[lane + 32]);
        hs[iA*64 + lane]      = hsum(a0A) + b0;
        hs[iA*64 + lane + 32] = hsum(a1A) + b1;
        hs[iB*64 + lane]      = hsum(a0B) + b0;
        hs[iB*64 + lane + 32] = hsum(a1B) + b1;
    }

    // ---------- layers ----------
    for (int l = 0; l < 2; l++) {
        __syncthreads();
        float* xsr = (l == 0) ? xs0 : xs1;
        float* xsw = (l == 0) ? xs1 : xs0;
        stagePairs<64>(WA, We1 + l * 8448, tid);   // rows 0..127 paired
        stagePairs<32>(WB, We2 + l * 4096, tid);
        if (tid < 132) {   // radial per edge
            int e = tid, i = e / 11, tt = e - 11 * i, j = tt + (tt >= i);
            float s0 = 0.f, s1 = 0.f, s2 = 0.f, s3 = 0.f;
            #pragma unroll
            for (int d = 0; d < 3; d++) {
                float d0 = xsr[i*12 + d*4 + 0] - xsr[j*12 + d*4 + 0]; s0 += d0*d0;
                float d1 = xsr[i*12 + d*4 + 1] - xsr[j*12 + d*4 + 1]; s1 += d1*d1;
                float d2 = xsr[i*12 + d*4 + 2] - xsr[j*12 + d*4 + 2]; s2 += d2*d2;
                float d3 = xsr[i*12 + d*4 + 3] - xsr[j*12 + d*4 + 3]; s3 += d3*d3;
            }
            ((float4*)rad)[e] = make_float4(s0, s1, s2, s3);
        }
        __syncthreads();

        // ---- P-phase: P1 in regs, P2 -> smem (FFMA2) ----
        float PiA0, PiA1, PiB0, PiB1;
        {
            u64 a0A = 0ull, a1A = 0ull, a2A = 0ull, a3A = 0ull;
            u64 a0B = 0ull, a1B = 0ull, a2B = 0ull, a3B = 0ull;
            #pragma unroll
            for (int k2 = 0; k2 < 32; k2++) {
                u64 hpA = ld64s(&hs[iA*64 + 2*k2]);
                u64 hpB = ld64s(&hs[iB*64 + 2*k2]);
                u64 w0 = WA2[k2*64 + lane],        w1 = WA2[k2*64 + lane + 32];
                u64 w2 = WA2[(32+k2)*64 + lane],   w3 = WA2[(32+k2)*64 + lane + 32];
                fma2(a0A, w0, hpA); fma2(a1A, w1, hpA);
                fma2(a2A, w2, hpA); fma2(a3A, w3, hpA);
                fma2(a0B, w0, hpB); fma2(a1B, w1, hpB);
                fma2(a2B, w2, hpB); fma2(a3B, w3, hpB);
            }
            float b0 = __ldg(&be1[l*64 + lane]), b1 = __ldg(&be1[l*64 + lane + 32]);
            PiA0 = hsum(a0A) + b0; PiA1 = hsum(a1A) + b1;
            PiB0 = hsum(a0B) + b0; PiB1 = hsum(a1B) + b1;
            ((float2*)P2p)[iA*32 + lane] = make_float2(hsum(a2A), hsum(a3A));
            ((float2*)P2p)[iB*32 + lane] = make_float2(hsum(a2B), hsum(a3B));
        }
        __syncthreads();

        // ---- edge phase: warp owns nodes iA, iB (22 edges, batch 6) ----
        {
            const float4 wxA = __ldg((const float4*)&Wx[l*256 + lane*4]);
            const float4 wxB = __ldg((const float4*)&Wx[l*256 + (lane+32)*4]);
            const float4 bxv = __ldg((const float4*)&bx[l*4]);
            const float be2a = __ldg(&be2[l*64 + lane]);
            const float be2b = __ldg(&be2[l*64 + lane + 32]);
            float wrA[4], wrB[4];
            #pragma unroll
            for (int v = 0; v < 4; v++) {
                wrA[v] = __ldg(&We1[l*8448 + (128+v)*64 + lane]);
                wrB[v] = __ldg(&We1[l*8448 + (128+v)*64 + lane + 32]);
            }
            const float xiA = (lane < 12) ? xsr[iA*12 + lane] : 0.f;
            const float xiB = (lane < 12) ? xsr[iB*12 + lane] : 0.f;
            float agA0 = 0.f, agB0 = 0.f, agA1 = 0.f, agB1 = 0.f;
            float dx0 = 0.f, dx1 = 0.f;
            float* msw = ms + w * 384;
            const bool lb0 = lane & 1, lb1 = lane & 2;

            #pragma unroll
            for (int g0 = 0; g0 < 22; g0 += 6) {
                const int cnt = (22 - g0 < 6) ? (22 - g0) : 6;
                // MLP1 (scalar)
                #pragma unroll
                for (int gg = 0; gg < 6; gg++) if (gg < cnt) {
                    const int t = g0 + gg;
                    const int i  = (t < 11) ? iA : iB;
                    const int tt = (t < 11) ? t : (t - 11);
                    const int j  = tt + (tt >= i);
                    float2 pj = ((const float2*)P2p)[j*32 + lane];
                    float4 rv = ((const float4*)rad)[i*11 + tt];
                    float P1a = (t < 11) ? PiA0 : PiB0;
                    float P1b = (t < 11) ? PiA1 : PiB1;
                    float aA = P1a + pj.x
                             + rv.x*wrA[0] + rv.y*wrA[1] + rv.z*wrA[2] + rv.w*wrA[3];
                    float aB = P1b + pj.y
                             + rv.x*wrB[0] + rv.y*wrB[1] + rv.z*wrB[2] + rv.w*wrB[3];
                    msw[gg*64 + lane]      = siluf(aA);
                    msw[gg*64 + lane + 32] = siluf(aB);
                }
                __syncwarp();
                // MLP2: FFMA2, weights amortized over up to 6 edges
                u64 acc0[6], acc1[6];
                #pragma unroll
                for (int gg = 0; gg < 6; gg++) { acc0[gg] = 0ull; acc1[gg] = 0ull; }
                #pragma unroll
                for (int k4 = 0; k4 < 16; k4++) {
                    u64 w00 = WB2[(2*k4)*64 + lane];
                    u64 w01 = WB2[(2*k4+1)*64 + lane];
                    u64 w10 = WB2[(2*k4)*64 + lane + 32];
                    u64 w11 = WB2[(2*k4+1)*64 + lane + 32];
                    #pragma unroll
                    for (int gg = 0; gg < 6; gg++) if (gg < cnt) {
                        float4 aq = *(const float4*)&msw[gg*64 + k4*4];
                        u64 a01 = pk(aq.x, aq.y);
                        u64 a23 = pk(aq.z, aq.w);
                        fma2(acc0[gg], w00, a01); fma2(acc0[gg], w01, a23);
                        fma2(acc1[gg], w10, a01); fma2(acc1[gg], w11, a23);
                    }
                }
                // epilogue: 6-shuffle multi-value reduce
                #pragma unroll
                for (int gg = 0; gg < 6; gg++) if (gg < cnt) {
                    const int t = g0 + gg;
                    const int tt = (t < 11) ? t : (t - 11);
                    const int i  = (t < 11) ? iA : iB;
                    const int j  = tt + (tt >= i);
                    float m0  = siluf(hsum(acc0[gg]) + be2a);
                    float m1v = siluf(hsum(acc1[gg]) + be2b);
                    if (t < 11) { agA0 += m0; agB0 += m1v; }
                    else        { agA1 += m0; agB1 += m1v; }
                    float p0 = m0*wxA.x + m1v*wxB.x;
                    float p1 = m0*wxA.y + m1v*wxB.y;
                    float p2 = m0*wxA.z + m1v*wxB.z;
                    float p3 = m0*wxA.w + m1v*wxB.w;
                    float sA = __shfl_xor_sync(0xffffffffu, lb0 ? p0 : p1, 1);
                    float A  = (lb0 ? p1 : p0) + sA;
                    float sC = __shfl_xor_sync(0xffffffffu, lb0 ? p2 : p3, 1);
                    float C  = (lb0 ? p3 : p2) + sC;
                    float sR = __shfl_xor_sync(0xffffffffu, lb1 ? A : C, 2);
                    float R  = (lb1 ? C : A) + sR;
                    R += __shfl_xor_sync(0xffffffffu, R, 4);
                    R += __shfl_xor_sync(0xffffffffu, R, 8);
                    R += __shfl_xor_sync(0xffffffffu, R, 16);
                    if (lane < 12) {
                        int v = lane & 3;
                        float wc = R + ((v == 0) ? bxv.x : (v == 1) ? bxv.y :
                                        (v == 2) ? bxv.z : bxv.w);
                        float xi = (t < 11) ? xiA : xiB;
                        float d  = (xi - xsr[j*12 + lane]) * wc;
                        if (t < 11) dx0 += d; else dx1 += d;
                    }
                }
                __syncwarp();
            }
            agg[iA*64 + lane]      = agA0;
            agg[iA*64 + lane + 32] = agB0;
            agg[iB*64 + lane]      = agA1;
            agg[iB*64 + lane + 32] = agB1;
            if (lane < 12) {
                xsw[iA*12 + lane] = xiA + dx0 * (1.0f / 11.0f);
                xsw[iB*12 + lane] = xiB + dx1 * (1.0f / 11.0f);
            }
        }
        __syncthreads();
        stagePairs<64>(WA, Wh1 + l * 8192, tid);
        stagePairs<32>(WB, Wh2 + l * 4096, tid);
        __syncthreads();

        // t1 = silu([h, agg] @ Wh1 + bh1)  (FFMA2)
        {
            u64 a0A = 0ull, a1A = 0ull, a0B = 0ull, a1B = 0ull;
            #pragma unroll
            for (int k2 = 0; k2 < 32; k2++) {
                u64 hpA = ld64s(&hs[iA*64 + 2*k2]);
                u64 hpB = ld64s(&hs[iB*64 + 2*k2]);
                u64 w0 = WA2[k2*64 + lane], w1 = WA2[k2*64 + lane + 32];
                fma2(a0A, w0, hpA); fma2(a1A, w1, hpA);
                fma2(a0B, w0, hpB); fma2(a1B, w1, hpB);
            }
            #pragma unroll
            for (int k2 = 0; k2 < 32; k2++) {
                u64 gpA = ld64s(&agg[iA*64 + 2*k2]);
                u64 gpB = ld64s(&agg[iB*64 + 2*k2]);
                u64 w0 = WA2[(32+k2)*64 + lane], w1 = WA2[(32+k2)*64 + lane + 32];
                fma2(a0A, w0, gpA); fma2(a1A, w1, gpA);
                fma2(a0B, w0, gpB); fma2(a1B, w1, gpB);
            }
            float b0 = __ldg(&bh1[l*64 + lane]), b1 = __ldg(&bh1[l*64 + lane + 32]);
            float s0A = siluf(hsum(a0A) + b0), s1A = siluf(hsum(a1A) + b1);
            float s0B = siluf(hsum(a0B) + b0), s1B = siluf(hsum(a1B) + b1);
            __syncthreads();   // P2p (aliased by t1s) fully consumed before overwrite
            t1s[iA*64 + lane] = s0A; t1s[iA*64 + lane + 32] = s1A;
            t1s[iB*64 + lane] = s0B; t1s[iB*64 + lane + 32] = s1B;
        }
        __syncthreads();
        // h += t1 @ Wh2 + bh2  (FFMA2)
        {
            u64 a0A = 0ull, a1A = 0ull, a0B = 0ull, a1B = 0ull;
            #pragma unroll
            for (int k2 = 0; k2 < 32; k2++) {
                u64 tpA = ld64s(&t1s[iA*64 + 2*k2]);
                u64 tpB = ld64s(&t1s[iB*64 + 2*k2]);
                u64 w0 = WB2[k2*64 + lane], w1 = WB2[k2*64 + lane + 32];
                fma2(a0A, w0, tpA); fma2(a1A, w1, tpA);
                fma2(a0B, w0, tpB); fma2(a1B, w1, tpB);
            }
            float b0 = __ldg(&bh2[l*64 + lane]), b1 = __ldg(&bh2[l*64 + lane + 32]);
            hs[iA*64 + lane]      += hsum(a0A) + b0;
            hs[iA*64 + lane + 32] += hsum(a1A) + b1;
            hs[iB*64 + lane]      += hsum(a0B) + b0;
            hs[iB*64 + lane + 32] += hsum(a1B) + b1;
        }
    }
    __syncthreads();
    // ---------- output: mu = x . w_act (final x in xs0) ----------
    if (tid < NAG * 3) {
        int a = tid / 3, d = tid - 3 * a;
        float mu = 0.f;
        #pragma unroll
        for (int v = 0; v < 4; v++) mu += xs0[a*12 + d*4 + v] * __ldg(&w_act[v]);
        out[(base + a) * 3 + d] = mu;
        out[NNODE * 3 + (base + a) * 3 + d] =
            -__ldg(&log_std[d]) - 0.91893853320467274178f;
    }
}

extern "C" void kernel_launch(void* const* d_in, const int* in_sizes, int n_in,
                              void* d_out, int out_size)
{
    (void)in_sizes; (void)n_in; (void)out_size;
    cudaFuncSetAttribute(egnn_kernel,
                         cudaFuncAttributeMaxDynamicSharedMemorySize, SMEM_BYTES);
    egnn_kernel<<<NENV, TPB, SMEM_BYTES>>>(
        (const float*)d_in[0],  (const float*)d_in[1],
        (const float*)d_in[2],  (const float*)d_in[3],
        (const float*)d_in[4],  (const float*)d_in[5],
        (const float*)d_in[6],  (const float*)d_in[7],
        (const float*)d_in[8],  (const float*)d_in[9],
        (const float*)d_in[10], (const float*)d_in[11],
        (const float*)d_in[12], (const float*)d_in[13],
        (const float*)d_in[14], (const float*)d_in[15],
        (float*)d_out);
}